// round 10
// baseline (speedup 1.0000x reference)
#include <cuda_runtime.h>
#include <cstdint>

#define CIN     32
#define COUT    32
#define KTAP    27
#define THREADS 320
#define NWARP   10
#define MAX_N   131072
#define BN_EPS  1e-3f

#define W_TILE  4096            // one tap's B tile: 32 rows x 128B
#define W_BYTES (KTAP * W_TILE) // 110592
#define DYN_SMEM (1024 + W_BYTES)   // 111616

// ---------------- device scratch ----------------
__device__ __align__(128) float g_xT[(size_t)MAX_N * CIN];   // x: [N][32] cin-permuted, tf32-rounded
__device__ __align__(128) float g_wpre[KTAP * 1024];         // pre-swizzled tf32 B tiles
__device__ __align__(128) int   g_neighT[(size_t)KTAP * MAX_N]; // neigh transposed [k][node]
__device__ __align__(128) float g_y[(size_t)COUT * MAX_N];   // pre-BN result [Cout][N]
__device__ float g_sum[COUT];
__device__ float g_sq[COUT];

// cin permutation: storage float f (0..31) within a node row <-> original cin.
static __device__ __forceinline__ int cin_of_f(int f) {
    int s2 = f >> 4, tig = (f >> 2) & 3, e = f & 3;
    return 16 * s2 + 8 * (e >> 1) + 4 * (e & 1) + tig;
}

// ---------------- PTX helpers ----------------
static __device__ __forceinline__ uint32_t smem_u32(const void* p) {
    uint32_t a;
    asm("{ .reg .u64 t; cvta.to.shared.u64 t, %1; cvt.u32.u64 %0, t; }" : "=r"(a) : "l"(p));
    return a;
}
static __device__ __forceinline__ void cp16(uint32_t dst, const void* src) {
    asm volatile("cp.async.cg.shared.global [%0], [%1], 16;" :: "r"(dst), "l"(src) : "memory");
}
static __device__ __forceinline__ void lds4u(uint32_t& x, uint32_t& y, uint32_t& z, uint32_t& w,
                                             uint32_t a) {
    asm volatile("ld.shared.v4.b32 {%0,%1,%2,%3}, [%4];"
                 : "=r"(x), "=r"(y), "=r"(z), "=r"(w) : "r"(a));
}
static __device__ __forceinline__ uint32_t tf32_rna(float v) {
    uint32_t r;
    asm("cvt.rna.tf32.f32 %0, %1;" : "=r"(r) : "f"(v));
    return r;
}
static __device__ __forceinline__ void mma8(float* c, float a0, float a1, float a2,
                                            float a3, uint32_t b0, uint32_t b1) {
    asm volatile(
        "mma.sync.aligned.m16n8k8.row.col.f32.tf32.tf32.f32 "
        "{%0,%1,%2,%3}, {%4,%5,%6,%7}, {%8,%9}, {%0,%1,%2,%3};"
        : "+f"(c[0]), "+f"(c[1]), "+f"(c[2]), "+f"(c[3])
        : "r"(__float_as_uint(a0)), "r"(__float_as_uint(a1)),
          "r"(__float_as_uint(a2)), "r"(__float_as_uint(a3)), "r"(b0), "r"(b1));
}

// direct A-fragment load: 8 float4 per thread = rows gid+8r, 32B tig-slice each.
static __device__ __forceinline__ void loadA(float4 a[8], int idxlane, int gid, int tig) {
#pragma unroll
    for (int r = 0; r < 4; ++r) {
        int node = __shfl_sync(0xffffffffu, idxlane, (r << 3) + gid);
        const float4* row = reinterpret_cast<const float4*>(g_xT + (size_t)node * CIN);
        a[r * 2 + 0] = row[tig];       // s2 = 0 half
        a[r * 2 + 1] = row[tig + 4];   // s2 = 1 half
    }
}

// ---------------- kernel 1: fused prep (transpose | neighT | wprep+init) ----------------
__global__ void prep_kernel(const float* __restrict__ in, const int* __restrict__ neigh,
                            const float* __restrict__ w, int N,
                            int nT, int nN, int nW) {
    int blk = blockIdx.x;
    if (blk < nT) {
        __shared__ float tile[32][33];
        int tx = threadIdx.x & 31, ty = threadIdx.x >> 5;
        int cm = cin_of_f(tx);
#pragma unroll 1
        for (int s = 0; s < 4; ++s) {
            int nb = (blk * 4 + s) * 32;
            if (nb >= N) break;
#pragma unroll
            for (int j = 0; j < 4; ++j) {
                int c = ty + j * 8, n = nb + tx;
                if (n < N) tile[c][tx] = in[(size_t)c * N + n];
            }
            __syncthreads();
#pragma unroll
            for (int j = 0; j < 4; ++j) {
                int nl = ty + j * 8, n = nb + nl;
                if (n < N)
                    g_xT[(size_t)n * CIN + tx] = __uint_as_float(tf32_rna(tile[cm][nl]));
            }
            __syncthreads();
        }
        return;
    }
    blk -= nT;
    if (blk < nN) {
        __shared__ int sb[8][864];
        int warp = threadIdx.x >> 5, lane = threadIdx.x & 31;
        int base = (blk * 8 + warp) * 32;
        const long fb = (long)base * KTAP;
        const long total = (long)N * KTAP;
#pragma unroll
        for (int j = 0; j < KTAP; ++j) {
            long p = fb + j * 32 + lane;
            sb[warp][j * 32 + lane] = (p < total) ? neigh[p] : 0;
        }
        __syncwarp();
        int node = base + lane;
        if (node < N) {
#pragma unroll
            for (int k = 0; k < KTAP; ++k)
                g_neighT[(size_t)k * N + node] = sb[warp][lane * KTAP + k];
        }
        return;
    }
    blk -= nN;
    if (blk < nW) {
        if (blk == 0 && threadIdx.x < COUT) {
            g_sum[threadIdx.x] = 0.f;
            g_sq[threadIdx.x]  = 0.f;
        }
        int i = blk * blockDim.x + threadIdx.x;
        if (i >= KTAP * 1024) return;
        int k = i >> 10, r = i & 1023;
        int n = r >> 5, f = r & 31;
        int chunk = f >> 2, e = f & 3;
        int cin = cin_of_f(f);
        float v = w[((size_t)k * CIN + cin) * COUT + n];
        int cs = chunk ^ (n & 7);
        g_wpre[k * 1024 + n * 32 + cs * 4 + e] = __uint_as_float(tf32_rna(v));
    }
}

// ---------------- kernel 2: direct-LDG gather + mma.sync tf32 conv + fused BN stats ------
__global__ void __launch_bounds__(THREADS)
conv_mma_kernel(int N, int nchunks) {
    extern __shared__ char dsm[];
    __shared__ float s_sum[COUT], s_sq[COUT];
    const int tid  = threadIdx.x;
    const int warp = tid >> 5, lane = tid & 31;
    const int gid  = lane >> 2, tig = lane & 3;

    const uint32_t sbase = (smem_u32(dsm) + 1023u) & ~1023u;
    const uint32_t wbase = sbase;

    if (tid < COUT) { s_sum[tid] = 0.f; s_sq[tid] = 0.f; }

    // ---- load all 27 pre-swizzled B tiles (one time) ----
    for (int i = tid; i < W_BYTES / 16; i += THREADS)
        cp16(wbase + i * 16, reinterpret_cast<const char*>(g_wpre) + i * 16);
    asm volatile("cp.async.commit_group;" ::: "memory");
    asm volatile("cp.async.wait_group 0;" ::: "memory");
    __syncthreads();

    float rs[4][2], rq[4][2];
#pragma unroll
    for (int nt = 0; nt < 4; ++nt) {
        rs[nt][0] = rs[nt][1] = 0.f;
        rq[nt][0] = rq[nt][1] = 0.f;
    }

    // per-warp, SM-striped work assignment
    const int wglob = warp * gridDim.x + blockIdx.x;
    const int nwtot = gridDim.x * NWARP;

    for (int ch = wglob; ch < nchunks; ch += nwtot) {
        const int base32 = ch << 5;
        const int mynode = base32 + lane;
        const bool nvalid = (mynode < N);

        float acc[2][4][4];
#pragma unroll
        for (int mt = 0; mt < 2; ++mt)
#pragma unroll
            for (int nt = 0; nt < 4; ++nt)
#pragma unroll
                for (int q = 0; q < 4; ++q) acc[mt][nt][q] = 0.f;

        float4 a0[8], a1[8];
        int i1;
        {
            int i0 = nvalid ? g_neighT[mynode] : 0;              // tap 0 indices
            loadA(a0, i0, gid, tig);
            i1 = nvalid ? g_neighT[(size_t)N + mynode] : 0;      // tap 1 indices
        }

#pragma unroll 1
        for (int k = 0; k < KTAP; k += 2) {
            // start A loads for tap k+1 while computing tap k
            if (k + 1 < KTAP) loadA(a1, i1, gid, tig);
            int i2 = 0;
            if (k + 2 < KTAP) i2 = nvalid ? g_neighT[(size_t)(k + 2) * N + mynode] : 0;

            // ---- compute tap k (a0) ----
            {
                const uint32_t wtap = wbase + (uint32_t)k * W_TILE;
#pragma unroll
                for (int s2 = 0; s2 < 2; ++s2) {
                    const uint32_t ch4 = (uint32_t)((((s2 << 2) | tig) ^ gid) << 4);
                    uint32_t B0[4], B1[4], B2[4], B3[4];
#pragma unroll
                    for (int nt = 0; nt < 4; ++nt)
                        lds4u(B0[nt], B1[nt], B2[nt], B3[nt],
                              wtap + (uint32_t)((nt * 8 + gid) * 128) + ch4);
#pragma unroll
                    for (int mt = 0; mt < 2; ++mt) {
                        float4 f0 = a0[mt * 4 + s2];      // row mt*16+gid
                        float4 f1 = a0[mt * 4 + 2 + s2];  // row mt*16+gid+8
#pragma unroll
                        for (int nt = 0; nt < 4; ++nt) {
                            mma8(acc[mt][nt], f0.x, f1.x, f0.y, f1.y, B0[nt], B1[nt]);
                            mma8(acc[mt][nt], f0.z, f1.z, f0.w, f1.w, B2[nt], B3[nt]);
                        }
                    }
                }
            }

            if (k + 1 < KTAP) {
                // start A loads for tap k+2 while computing tap k+1
                if (k + 2 < KTAP) loadA(a0, i2, gid, tig);
                if (k + 3 < KTAP) i1 = nvalid ? g_neighT[(size_t)(k + 3) * N + mynode] : 0;

                const uint32_t wtap = wbase + (uint32_t)(k + 1) * W_TILE;
#pragma unroll
                for (int s2 = 0; s2 < 2; ++s2) {
                    const uint32_t ch4 = (uint32_t)((((s2 << 2) | tig) ^ gid) << 4);
                    uint32_t B0[4], B1[4], B2[4], B3[4];
#pragma unroll
                    for (int nt = 0; nt < 4; ++nt)
                        lds4u(B0[nt], B1[nt], B2[nt], B3[nt],
                              wtap + (uint32_t)((nt * 8 + gid) * 128) + ch4);
#pragma unroll
                    for (int mt = 0; mt < 2; ++mt) {
                        float4 f0 = a1[mt * 4 + s2];
                        float4 f1 = a1[mt * 4 + 2 + s2];
#pragma unroll
                        for (int nt = 0; nt < 4; ++nt) {
                            mma8(acc[mt][nt], f0.x, f1.x, f0.y, f1.y, B0[nt], B1[nt]);
                            mma8(acc[mt][nt], f0.z, f1.z, f0.w, f1.w, B2[nt], B3[nt]);
                        }
                    }
                }
            }
        }

        // epilogue: store y + accumulate BN stats in registers
#pragma unroll
        for (int mt = 0; mt < 2; ++mt) {
            int node = base32 + (mt << 4) + gid;
            bool v0 = (node < N), v1 = (node + 8 < N);
#pragma unroll
            for (int nt = 0; nt < 4; ++nt) {
                int cb = (nt << 3) + (tig << 1);
                if (v0) {
                    float a = acc[mt][nt][0], c = acc[mt][nt][1];
                    g_y[(size_t)cb * N + node]       = a;
                    g_y[(size_t)(cb + 1) * N + node] = c;
                    rs[nt][0] += a; rq[nt][0] += a * a;
                    rs[nt][1] += c; rq[nt][1] += c * c;
                }
                if (v1) {
                    float a = acc[mt][nt][2], c = acc[mt][nt][3];
                    g_y[(size_t)cb * N + node + 8]       = a;
                    g_y[(size_t)(cb + 1) * N + node + 8] = c;
                    rs[nt][0] += a; rq[nt][0] += a * a;
                    rs[nt][1] += c; rq[nt][1] += c * c;
                }
            }
        }
    }

    // ---- reduce BN stats ----
#pragma unroll
    for (int nt = 0; nt < 4; ++nt)
#pragma unroll
        for (int q = 0; q < 2; ++q) {
#pragma unroll
            for (int o = 4; o <= 16; o <<= 1) {
                rs[nt][q] += __shfl_xor_sync(~0u, rs[nt][q], o);
                rq[nt][q] += __shfl_xor_sync(~0u, rq[nt][q], o);
            }
        }
    if (gid == 0) {
#pragma unroll
        for (int nt = 0; nt < 4; ++nt)
#pragma unroll
            for (int q = 0; q < 2; ++q) {
                int cb = (nt << 3) + (tig << 1) + q;
                atomicAdd(&s_sum[cb], rs[nt][q]);
                atomicAdd(&s_sq[cb],  rq[nt][q]);
            }
    }
    __syncthreads();
    if (tid < COUT) {
        atomicAdd(&g_sum[tid], s_sum[tid]);
        atomicAdd(&g_sq[tid],  s_sq[tid]);
    }
}

// ---------------- kernel 3: finalize (per-block) + normalize + write output ----------------
__global__ void norm_kernel(float* __restrict__ out, const float* __restrict__ gamma,
                            const float* __restrict__ beta, int N) {
    __shared__ float s_scale[COUT], s_shift[COUT];
    if (threadIdx.x < COUT) {
        int d = threadIdx.x;
        float mean = g_sum[d] / (float)N;
        float var  = g_sq[d] / (float)N - mean * mean;
        float inv  = rsqrtf(var + BN_EPS);
        float sc   = gamma[d] * inv;
        s_scale[d] = sc;
        s_shift[d] = beta[d] - mean * sc;
    }
    __syncthreads();
    int i = blockIdx.x * blockDim.x + threadIdx.x;
    int total4 = (COUT * N) >> 2;
    if (i >= total4) return;
    int d = (i << 2) / N;
    float4 v = reinterpret_cast<const float4*>(g_y)[i];
    float sc = s_scale[d], sh = s_shift[d];
    v.x = v.x * sc + sh;
    v.y = v.y * sc + sh;
    v.z = v.z * sc + sh;
    v.w = v.w * sc + sh;
    reinterpret_cast<float4*>(out)[i] = v;
}

// ---------------- launch ----------------
extern "C" void kernel_launch(void* const* d_in, const int* in_sizes, int n_in,
                              void* d_out, int out_size) {
    const float* data_in = (const float*)d_in[0];   // [1, Cin, N, 1]
    const int*   neigh   = (const int*)d_in[1];     // [N, 27]
    const float* weight  = (const float*)d_in[2];   // [27, Cin, Cout]
    const float* gamma   = (const float*)d_in[3];
    const float* beta    = (const float*)d_in[4];
    float*       out     = (float*)d_out;

    const int N = in_sizes[0] / CIN;
    const int nchunks = (N + 31) / 32;

    int dev = 0, nsm = 148;
    cudaGetDevice(&dev);
    cudaDeviceGetAttribute(&nsm, cudaDevAttrMultiProcessorCount, dev);
    if (nsm <= 0) nsm = 148;
    int grid = nsm;
    int maxctas = (nchunks + NWARP - 1) / NWARP;
    if (grid > maxctas) grid = maxctas;

    cudaFuncSetAttribute(conv_mma_kernel,
                         cudaFuncAttributeMaxDynamicSharedMemorySize, DYN_SMEM);

    const int nT = (N + 127) / 128;                  // transpose blocks (4 subtiles each)
    const int nN = (N + 255) / 256;                  // neighT blocks
    const int nW = (KTAP * 1024 + 255) / 256;        // wprep blocks
    prep_kernel<<<nT + nN + nW, 256>>>(data_in, neigh, weight, N, nT, nN, nW);

    conv_mma_kernel<<<grid, THREADS, DYN_SMEM>>>(N, nchunks);

    {
        int total4 = (COUT * N) / 4;
        norm_kernel<<<(total4 + 255) / 256, 256>>>(out, gamma, beta, N);
    }
}

// round 11
// speedup vs baseline: 1.0957x; 1.0957x over previous
#include <cuda_runtime.h>
#include <cstdint>

#define CIN     32
#define COUT    32
#define KTAP    27
#define THREADS 416
#define NWARP   13
#define MAX_N   131072
#define BN_EPS  1e-3f

#define W_TILE  4096            // one tap's B tile: 32 rows x 128B
#define W_BYTES (KTAP * W_TILE) // 110592
#define ABUF    4096            // per-warp A buffer: 32 rows x 128B
#define NBUF    2
#define DYN_SMEM (1024 + W_BYTES + NWARP * NBUF * ABUF)   // 218112

// ---------------- device scratch ----------------
__device__ __align__(128) float g_xT[(size_t)MAX_N * CIN];   // x: [N][32] cin-permuted, tf32-rounded
__device__ __align__(128) float g_wpre[KTAP * 1024];         // pre-swizzled tf32 B tiles
__device__ __align__(128) int   g_neighT[(size_t)KTAP * MAX_N]; // neigh transposed [k][node]
__device__ __align__(128) float g_y[(size_t)COUT * MAX_N];   // pre-BN result [Cout][N]
__device__ float g_sum[COUT];
__device__ float g_sq[COUT];

// cin permutation: storage float f (0..31) within a node row <-> original cin.
static __device__ __forceinline__ int cin_of_f(int f) {
    int s2 = f >> 4, tig = (f >> 2) & 3, e = f & 3;
    return 16 * s2 + 8 * (e >> 1) + 4 * (e & 1) + tig;
}

// ---------------- PTX helpers ----------------
static __device__ __forceinline__ uint32_t smem_u32(const void* p) {
    uint32_t a;
    asm("{ .reg .u64 t; cvta.to.shared.u64 t, %1; cvt.u32.u64 %0, t; }" : "=r"(a) : "l"(p));
    return a;
}
static __device__ __forceinline__ void cp16(uint32_t dst, const void* src) {
    asm volatile("cp.async.cg.shared.global [%0], [%1], 16;" :: "r"(dst), "l"(src) : "memory");
}
#define CP_COMMIT() asm volatile("cp.async.commit_group;" ::: "memory")

static __device__ __forceinline__ void lds4u(uint32_t& x, uint32_t& y, uint32_t& z, uint32_t& w,
                                             uint32_t a) {
    asm volatile("ld.shared.v4.b32 {%0,%1,%2,%3}, [%4];"
                 : "=r"(x), "=r"(y), "=r"(z), "=r"(w) : "r"(a));
}
static __device__ __forceinline__ uint32_t tf32_rna(float v) {
    uint32_t r;
    asm("cvt.rna.tf32.f32 %0, %1;" : "=r"(r) : "f"(v));
    return r;
}
static __device__ __forceinline__ void mma8(float* c, uint32_t a0, uint32_t a1, uint32_t a2,
                                            uint32_t a3, uint32_t b0, uint32_t b1) {
    asm volatile(
        "mma.sync.aligned.m16n8k8.row.col.f32.tf32.tf32.f32 "
        "{%0,%1,%2,%3}, {%4,%5,%6,%7}, {%8,%9}, {%0,%1,%2,%3};"
        : "+f"(c[0]), "+f"(c[1]), "+f"(c[2]), "+f"(c[3])
        : "r"(a0), "r"(a1), "r"(a2), "r"(a3), "r"(b0), "r"(b1));
}

// cooperative gather: one warp fills 32 rows (128B each); each cp.async covers
// 4 rows x 8 lanes -> 4 L2 lines per instruction; writes stay in one 512B window.
static __device__ __forceinline__ void gather32(uint32_t dst_buf, int idx_reg, int lane) {
    const int rsub  = lane >> 3;       // 0..3
    const int chunk = lane & 7;        // 16B chunk within row
#pragma unroll
    for (int j = 0; j < 8; ++j) {
        int row = j * 4 + rsub;
        int src_idx = __shfl_sync(0xffffffffu, idx_reg, row);
        const char* src = reinterpret_cast<const char*>(g_xT + (size_t)src_idx * CIN)
                          + (chunk << 4);
        uint32_t dst = dst_buf + (uint32_t)(row << 7)
                       + (uint32_t)((chunk ^ (row & 7)) << 4);
        cp16(dst, src);
    }
}

// ---------------- kernel 1: fused prep (transpose | neighT | wprep+init) ----------------
__global__ void prep_kernel(const float* __restrict__ in, const int* __restrict__ neigh,
                            const float* __restrict__ w, int N,
                            int nT, int nN, int nW) {
    int blk = blockIdx.x;
    if (blk < nT) {
        // transpose + cin-permute + tf32 RNA round: [Cin,N] -> [N][32]
        __shared__ float tile[32][33];
        int tx = threadIdx.x & 31, ty = threadIdx.x >> 5;
        int cm = cin_of_f(tx);
#pragma unroll 1
        for (int s = 0; s < 4; ++s) {
            int nb = (blk * 4 + s) * 32;
            if (nb >= N) break;
#pragma unroll
            for (int j = 0; j < 4; ++j) {
                int c = ty + j * 8, n = nb + tx;
                if (n < N) tile[c][tx] = in[(size_t)c * N + n];
            }
            __syncthreads();
#pragma unroll
            for (int j = 0; j < 4; ++j) {
                int nl = ty + j * 8, n = nb + nl;
                if (n < N)
                    g_xT[(size_t)n * CIN + tx] = __uint_as_float(tf32_rna(tile[cm][nl]));
            }
            __syncthreads();
        }
        return;
    }
    blk -= nT;
    if (blk < nN) {
        // neigh transpose [N][27] -> [27][N], 8 warps x 32 nodes per block
        __shared__ int sb[8][864];
        int warp = threadIdx.x >> 5, lane = threadIdx.x & 31;
        int base = (blk * 8 + warp) * 32;
        const long fb = (long)base * KTAP;
        const long total = (long)N * KTAP;
#pragma unroll
        for (int j = 0; j < KTAP; ++j) {
            long p = fb + j * 32 + lane;
            sb[warp][j * 32 + lane] = (p < total) ? neigh[p] : 0;
        }
        __syncwarp();
        int node = base + lane;
        if (node < N) {
#pragma unroll
            for (int k = 0; k < KTAP; ++k)
                g_neighT[(size_t)k * N + node] = sb[warp][lane * KTAP + k];
        }
        return;
    }
    blk -= nN;
    if (blk < nW) {
        if (blk == 0 && threadIdx.x < COUT) {
            g_sum[threadIdx.x] = 0.f;
            g_sq[threadIdx.x]  = 0.f;
        }
        int i = blk * blockDim.x + threadIdx.x;   // over 27*1024 elems
        if (i >= KTAP * 1024) return;
        int k = i >> 10, r = i & 1023;
        int n = r >> 5, f = r & 31;               // n = cout row, f = storage float
        int chunk = f >> 2, e = f & 3;
        int cin = cin_of_f(f);
        float v = w[((size_t)k * CIN + cin) * COUT + n];
        int cs = chunk ^ (n & 7);
        g_wpre[k * 1024 + n * 32 + cs * 4 + e] = __uint_as_float(tf32_rna(v));
    }
}

// ---------------- kernel 2: gather + mma.sync tf32 conv + fused BN stats ----------------
__global__ void __launch_bounds__(THREADS)
conv_mma_kernel(int N, int nchunks) {
    extern __shared__ char dsm[];
    __shared__ float s_sum[COUT], s_sq[COUT];
    const int tid  = threadIdx.x;
    const int warp = tid >> 5, lane = tid & 31;
    const int gid  = lane >> 2, tig = lane & 3;

    const uint32_t sbase = (smem_u32(dsm) + 1023u) & ~1023u;
    const uint32_t wbase = sbase;
    const uint32_t abase = sbase + W_BYTES + (uint32_t)warp * (NBUF * ABUF);

    if (tid < COUT) { s_sum[tid] = 0.f; s_sq[tid] = 0.f; }

    // ---- load all 27 pre-swizzled B tiles (one time) ----
    for (int i = tid; i < W_BYTES / 16; i += THREADS)
        cp16(wbase + i * 16, reinterpret_cast<const char*>(g_wpre) + i * 16);
    CP_COMMIT();
    asm volatile("cp.async.wait_group 0;" ::: "memory");
    __syncthreads();

    float rs[4][2], rq[4][2];
#pragma unroll
    for (int nt = 0; nt < 4; ++nt) {
        rs[nt][0] = rs[nt][1] = 0.f;
        rq[nt][0] = rq[nt][1] = 0.f;
    }

    // per-warp work assignment, SM-striped: every SM ends up with an even share
    // of the 32-node chunks regardless of which warp they land on.
    const int wglob  = warp * gridDim.x + blockIdx.x;
    const int nwtot  = gridDim.x * NWARP;

    for (int ch = wglob; ch < nchunks; ch += nwtot) {
        const int base32 = ch << 5;
        const int mynode = base32 + lane;
        const bool nvalid = (mynode < N);

        float acc[2][4][4];
#pragma unroll
        for (int mt = 0; mt < 2; ++mt)
#pragma unroll
            for (int nt = 0; nt < 4; ++nt)
#pragma unroll
                for (int q = 0; q < 4; ++q) acc[mt][nt][q] = 0.f;

        // prologue: gather taps 0..1
#pragma unroll
        for (int k = 0; k < NBUF; ++k) {
            int idx = nvalid ? g_neighT[(size_t)k * N + mynode] : 0;
            gather32(abase + (uint32_t)k * ABUF, idx, lane);
            CP_COMMIT();
        }

        int b = 0;
#pragma unroll 1
        for (int k = 0; k < KTAP; ++k) {
            if (k < KTAP - 1) asm volatile("cp.async.wait_group 1;" ::: "memory");
            else              asm volatile("cp.async.wait_group 0;" ::: "memory");
            __syncwarp();

            const uint32_t abuf = abase + (uint32_t)b * ABUF;
            const uint32_t wtap = wbase + (uint32_t)k * W_TILE;
#pragma unroll
            for (int s2 = 0; s2 < 2; ++s2) {
                const uint32_t ch4 = (uint32_t)((((s2 << 2) | tig) ^ gid) << 4);
                uint32_t B0[4], B1[4], B2[4], B3[4];
#pragma unroll
                for (int nt = 0; nt < 4; ++nt)
                    lds4u(B0[nt], B1[nt], B2[nt], B3[nt],
                          wtap + (uint32_t)((nt * 8 + gid) * 128) + ch4);
#pragma unroll
                for (int mt = 0; mt < 2; ++mt) {
                    uint32_t hx, hy, hz, hw, gx, gy, gz, gw;
                    lds4u(hx, hy, hz, hw, abuf + (uint32_t)((mt * 16 + gid) * 128) + ch4);
                    lds4u(gx, gy, gz, gw, abuf + (uint32_t)((mt * 16 + gid + 8) * 128) + ch4);
#pragma unroll
                    for (int nt = 0; nt < 4; ++nt) {
                        mma8(acc[mt][nt], hx, gx, hy, gy, B0[nt], B1[nt]);
                        mma8(acc[mt][nt], hz, gz, hw, gw, B2[nt], B3[nt]);
                    }
                }
            }

            if (k + NBUF < KTAP) {
                __syncwarp();
                int idx = nvalid ? g_neighT[(size_t)(k + NBUF) * N + mynode] : 0;
                gather32(abuf, idx, lane);
                CP_COMMIT();
            }
            b ^= 1;
        }

        // epilogue: store y + accumulate BN stats in registers
#pragma unroll
        for (int mt = 0; mt < 2; ++mt) {
            int node = base32 + (mt << 4) + gid;
            bool v0 = (node < N), v1 = (node + 8 < N);
#pragma unroll
            for (int nt = 0; nt < 4; ++nt) {
                int cb = (nt << 3) + (tig << 1);
                if (v0) {
                    float a = acc[mt][nt][0], c = acc[mt][nt][1];
                    g_y[(size_t)cb * N + node]       = a;
                    g_y[(size_t)(cb + 1) * N + node] = c;
                    rs[nt][0] += a; rq[nt][0] += a * a;
                    rs[nt][1] += c; rq[nt][1] += c * c;
                }
                if (v1) {
                    float a = acc[mt][nt][2], c = acc[mt][nt][3];
                    g_y[(size_t)cb * N + node + 8]       = a;
                    g_y[(size_t)(cb + 1) * N + node + 8] = c;
                    rs[nt][0] += a; rq[nt][0] += a * a;
                    rs[nt][1] += c; rq[nt][1] += c * c;
                }
            }
        }
    }

    // ---- reduce BN stats: shuffle over gid, shared atomics, one global atomic per CTA ----
#pragma unroll
    for (int nt = 0; nt < 4; ++nt)
#pragma unroll
        for (int q = 0; q < 2; ++q) {
#pragma unroll
            for (int o = 4; o <= 16; o <<= 1) {
                rs[nt][q] += __shfl_xor_sync(~0u, rs[nt][q], o);
                rq[nt][q] += __shfl_xor_sync(~0u, rq[nt][q], o);
            }
        }
    if (gid == 0) {
#pragma unroll
        for (int nt = 0; nt < 4; ++nt)
#pragma unroll
            for (int q = 0; q < 2; ++q) {
                int cb = (nt << 3) + (tig << 1) + q;
                atomicAdd(&s_sum[cb], rs[nt][q]);
                atomicAdd(&s_sq[cb],  rq[nt][q]);
            }
    }
    __syncthreads();
    if (tid < COUT) {
        atomicAdd(&g_sum[tid], s_sum[tid]);
        atomicAdd(&g_sq[tid],  s_sq[tid]);
    }
}

// ---------------- kernel 3: finalize (per-block) + normalize + write output ----------------
__global__ void norm_kernel(float* __restrict__ out, const float* __restrict__ gamma,
                            const float* __restrict__ beta, int N) {
    __shared__ float s_scale[COUT], s_shift[COUT];
    if (threadIdx.x < COUT) {
        int d = threadIdx.x;
        float mean = g_sum[d] / (float)N;
        float var  = g_sq[d] / (float)N - mean * mean;
        float inv  = rsqrtf(var + BN_EPS);
        float sc   = gamma[d] * inv;
        s_scale[d] = sc;
        s_shift[d] = beta[d] - mean * sc;
    }
    __syncthreads();
    int i = blockIdx.x * blockDim.x + threadIdx.x;
    int total4 = (COUT * N) >> 2;
    if (i >= total4) return;
    int d = (i << 2) / N;
    float4 v = reinterpret_cast<const float4*>(g_y)[i];
    float sc = s_scale[d], sh = s_shift[d];
    v.x = v.x * sc + sh;
    v.y = v.y * sc + sh;
    v.z = v.z * sc + sh;
    v.w = v.w * sc + sh;
    reinterpret_cast<float4*>(out)[i] = v;
}

// ---------------- launch ----------------
extern "C" void kernel_launch(void* const* d_in, const int* in_sizes, int n_in,
                              void* d_out, int out_size) {
    const float* data_in = (const float*)d_in[0];   // [1, Cin, N, 1]
    const int*   neigh   = (const int*)d_in[1];     // [N, 27]
    const float* weight  = (const float*)d_in[2];   // [27, Cin, Cout]
    const float* gamma   = (const float*)d_in[3];
    const float* beta    = (const float*)d_in[4];
    float*       out     = (float*)d_out;

    const int N = in_sizes[0] / CIN;
    const int nchunks = (N + 31) / 32;

    int dev = 0, nsm = 148;
    cudaGetDevice(&dev);
    cudaDeviceGetAttribute(&nsm, cudaDevAttrMultiProcessorCount, dev);
    if (nsm <= 0) nsm = 148;
    int grid = nsm;
    int maxctas = (nchunks + NWARP - 1) / NWARP;
    if (grid > maxctas) grid = maxctas;

    cudaFuncSetAttribute(conv_mma_kernel,
                         cudaFuncAttributeMaxDynamicSharedMemorySize, DYN_SMEM);

    const int nT = (N + 127) / 128;                  // transpose blocks (4 subtiles each)
    const int nN = (N + 255) / 256;                  // neighT blocks
    const int nW = (KTAP * 1024 + 255) / 256;        // wprep blocks
    prep_kernel<<<nT + nN + nW, 256>>>(data_in, neigh, weight, N, nT, nN, nW);

    conv_mma_kernel<<<grid, THREADS, DYN_SMEM>>>(N, nchunks);

    {
        int total4 = (COUT * N) / 4;
        norm_kernel<<<(total4 + 255) / 256, 256>>>(out, gamma, beta, N);
    }
}